// round 13
// baseline (speedup 1.0000x reference)
#include <cuda_runtime.h>

typedef unsigned long long ull;

// Scratch: q/kv projections (fp32). Pixel linear order: ((b*64+P)*64+R)*16 + (i*4+j)
__device__ __align__(16) float g_q [2u*64*64*16*256];  // 134 MB
__device__ __align__(16) float g_kv[2u*64*64*16*512];  // 268 MB

__device__ __forceinline__ float ex2f(float x) {
    float y; asm("ex2.approx.ftz.f32 %0, %1;" : "=f"(y) : "f"(x)); return y;
}
__device__ __forceinline__ ull pk(float lo, float hi) {
    ull r; asm("mov.b64 %0, {%1, %2};" : "=l"(r) : "f"(lo), "f"(hi)); return r;
}
__device__ __forceinline__ void upk(ull v, float& lo, float& hi) {
    asm("mov.b64 {%0, %1}, %2;" : "=f"(lo), "=f"(hi) : "l"(v));
}
__device__ __forceinline__ ull fma2(ull a, ull b, ull c) {
    ull d; asm("fma.rn.f32x2 %0, %1, %2, %3;" : "=l"(d) : "l"(a), "l"(b), "l"(c)); return d;
}
__device__ __forceinline__ ull mul2(ull a, ull b) {
    ull d; asm("mul.rn.f32x2 %0, %1, %2;" : "=l"(d) : "l"(a), "l"(b)); return d;
}
__device__ __forceinline__ float hsum2(ull v) {
    float lo, hi; upk(v, lo, hi); return lo + hi;
}

// ---------------------------------------------------------------------------
// Pass 1: proj = x @ w_in.T + b_in   (M=131072 px, N=768, K=128)  [R10-proven]
// ---------------------------------------------------------------------------
__global__ void proj_kernel(const float* __restrict__ x,
                            const float* __restrict__ w_in,
                            const float* __restrict__ b_in)
{
    __shared__ float  xs[64 * 128];
    __shared__ float4 ws4[64 * 16];

    const int t   = blockIdx.x;
    const int b   = t >> 10;
    const int P   = (t >> 4) & 63;
    const int R0  = (t & 15) << 2;
    const int tid = threadIdx.x;

    const float* xb = x + b * 128 * 65536;
    #pragma unroll 4
    for (int ii = 0; ii < 8; ii++) {
        int idx = tid + ii * 256;
        int c  = idx >> 4;
        int rj = idx & 15;
        int Rl = rj >> 2, j = rj & 3;
        int hh = (R0 + Rl) * 4 + j;
        float4 v = *(const float4*)(xb + (c * 256 + hh) * 256 + P * 4);
        int mb_ = Rl * 16 + j;
        xs[(mb_ + 0)  * 128 + c] = v.x;
        xs[(mb_ + 4)  * 128 + c] = v.y;
        xs[(mb_ + 8)  * 128 + c] = v.z;
        xs[(mb_ + 12) * 128 + c] = v.w;
    }

    const int tn = tid & 15;
    const int tm = tid >> 4;
    const int blk = ((b * 64 + P) * 64 + R0) * 16;
    const float4* xs4 = (const float4*)xs;

    for (int nc = 0; nc < 12; nc++) {
        const int n0 = nc * 64;
        ull accp[4][4];
        #pragma unroll
        for (int mm = 0; mm < 4; mm++)
            #pragma unroll
            for (int nn = 0; nn < 4; nn++) accp[mm][nn] = 0ULL;

        for (int kc = 0; kc < 2; kc++) {
            __syncthreads();
            #pragma unroll
            for (int ii = 0; ii < 4; ii++) {
                int idx = tid + ii * 256;
                int n = idx >> 4, kq = idx & 15;
                float4 v = *(const float4*)(w_in + (n0 + n) * 128 + kc * 64 + kq * 4);
                ws4[n * 16 + (kq ^ (n & 15))] = v;
            }
            __syncthreads();

            #pragma unroll
            for (int k4 = 0; k4 < 16; k4++) {
                ull a01[4], a23[4], b01[4], b23[4];
                #pragma unroll
                for (int mm = 0; mm < 4; mm++) {
                    float4 a = xs4[(tm + 16 * mm) * 32 + kc * 16 + k4];
                    a01[mm] = pk(a.x, a.y); a23[mm] = pk(a.z, a.w);
                }
                #pragma unroll
                for (int nn = 0; nn < 4; nn++) {
                    int n = tn + 16 * nn;
                    float4 v = ws4[n * 16 + (k4 ^ (n & 15))];
                    b01[nn] = pk(v.x, v.y); b23[nn] = pk(v.z, v.w);
                }
                #pragma unroll
                for (int mm = 0; mm < 4; mm++)
                    #pragma unroll
                    for (int nn = 0; nn < 4; nn++) {
                        accp[mm][nn] = fma2(a01[mm], b01[nn], accp[mm][nn]);
                        accp[mm][nn] = fma2(a23[mm], b23[nn], accp[mm][nn]);
                    }
            }
        }

        #pragma unroll
        for (int nn = 0; nn < 4; nn++) {
            int n = n0 + tn + 16 * nn;
            float bi = __ldg(b_in + n);
            #pragma unroll
            for (int mm = 0; mm < 4; mm++) {
                int m = tm + 16 * mm;
                float v = hsum2(accp[mm][nn]) + bi;
                if (n < 256) g_q [(size_t)(blk + m) * 256 + n]         = v;
                else         g_kv[(size_t)(blk + m) * 512 + (n - 256)] = v;
            }
        }
    }
}

// ---------------------------------------------------------------------------
// Pass 2: attention. 256 threads: warp = head (8 warps), lane = blk*16 + qq.
// All k/v LDS.128 are warp-uniform broadcasts. Per-lane +inf bias masks the
// row-inactive block (exactly the reference -inf cut).
// Static smem pool[10240]: [kvbuf 16x512 = 8192][pce 2048]; obuf (32x260) reuses.
// ---------------------------------------------------------------------------
__global__ __launch_bounds__(256) void attn_kernel(
    const float* __restrict__ w_out, const float* __restrict__ b_out,
    const float* __restrict__ pce,   float* __restrict__ out)
{
    __shared__ float pool[10240];
    float* kvbuf = pool;
    float* pcesm = pool + 8192;

    const int bx  = blockIdx.x;
    const int b   = bx >> 11;
    const int P   = (bx >> 5) & 63;
    const int R0  = (bx & 31) << 1;
    const int tid = threadIdx.x;
    const int h   = tid >> 5;          // warp = head
    const int ln  = tid & 31;
    const int blk = ln >> 4;           // which R block this lane's query is in
    const int qq  = ln & 15;
    const int iq  = qq >> 2, jq = qq & 3;

    const float LOG2E = 1.4426950408889634f;
    for (int i = tid; i < 2048; i += 256) pcesm[i] = pce[i] * LOG2E;

    // query row (packed f32x2), pre-scaled by (1/sqrt(DH)) * log2(e)
    const float SC = 0.17677669529663687f * LOG2E;
    ull qa[16];
    {
        const float4* qp = (const float4*)(g_q +
            (size_t)(((b * 64 + P) * 64 + (R0 + blk)) * 16 + qq) * 256 + h * 32);
        #pragma unroll
        for (int d4 = 0; d4 < 8; d4++) {
            float4 v = qp[d4];
            qa[d4*2+0] = pk(v.x * SC, v.y * SC);
            qa[d4*2+1] = pk(v.z * SC, v.w * SC);
        }
    }

    ull acc[16];
    #pragma unroll
    for (int d = 0; d < 16; d++) acc[d] = 0ULL;
    float mrun = -1e30f, l = 0.f;

    const float INF = __int_as_float(0x7f800000);

    // kv tile list: rows R0-1..R0+2, cols P-1..P+1 (frame skip == -inf cut)
    int tP[12], tR[12], tC[12];
    int nt = 0;
    for (int rr = 0; rr < 4; rr++) {
        int Rp = R0 - 1 + rr;
        if (Rp < 0 || Rp > 63) continue;
        for (int cc = 0; cc < 3; cc++) {
            int Pp = P - 1 + cc;
            if (Pp < 0 || Pp > 63) continue;
            tP[nt] = Pp; tR[nt] = Rp; tC[nt] = rr * 4 + cc; nt++;
        }
    }

    for (int t = 0; t < nt; t++) {
        __syncthreads();   // previous tile consumed (and pcesm on first iter)
        {
            const float4* src = (const float4*)(g_kv + (size_t)((b * 64 + tP[t]) * 64 + tR[t]) * 16 * 512);
            float4* dst = (float4*)kvbuf;
            #pragma unroll
            for (int ii = 0; ii < 8; ii++) {
                int idx = tid + ii * 256;
                dst[idx] = src[idx];
            }
        }
        __syncthreads();

        const int rr = tC[t] >> 2, cc = tC[t] & 3;
        // lane-active: block 0 sees rows 0..2, block 1 sees rows 1..3
        const bool act = blk ? (rr >= 1) : (rr <= 2);
        const int dr = rr - blk, dp = cc;

        float s[16];
        #pragma unroll
        for (int kp = 0; kp < 16; kp++) {
            const float* kr = kvbuf + kp * 512 + h * 32;   // warp-uniform
            ull d0 = 0ULL;
            #pragma unroll
            for (int dd = 0; dd < 8; dd++) {
                float4 kk = *(const float4*)(kr + dd * 4);
                d0 = fma2(qa[dd*2+0], pk(kk.x, kk.y), d0);
                d0 = fma2(qa[dd*2+1], pk(kk.z, kk.w), d0);
            }
            int ik = kp >> 2, jk = kp & 3;
            int nu  = dp * 4 + ik + 4 - iq;
            int ntt = dr * 4 + jk + 4 - jq;
            float bias = act ? pcesm[h * 256 + nu * 16 + ntt] : INF;
            s[kp] = hsum2(d0) - bias;       // inactive lane -> -inf -> p = 0
        }

        float mb = s[0];
        #pragma unroll
        for (int kp = 1; kp < 16; kp++) mb = fmaxf(mb, s[kp]);
        float mn = fmaxf(mrun, mb);
        float f  = ex2f(mrun - mn);
        mrun = mn;
        l *= f;
        ull fp = pk(f, f);
        #pragma unroll
        for (int d = 0; d < 16; d++) acc[d] = mul2(acc[d], fp);

        float sp = 0.f;
        #pragma unroll
        for (int kp = 0; kp < 16; kp++) {
            float p = ex2f(s[kp] - mn);
            sp += p;
            ull pp = pk(p, p);
            const float* vr = kvbuf + kp * 512 + 256 + h * 32;   // warp-uniform
            #pragma unroll
            for (int dd = 0; dd < 8; dd++) {
                float4 vv = *(const float4*)(vr + dd * 4);
                acc[dd*2+0] = fma2(pp, pk(vv.x, vv.y), acc[dd*2+0]);
                acc[dd*2+1] = fma2(pp, pk(vv.z, vv.w), acc[dd*2+1]);
            }
        }
        l += sp;
    }

    // Normalize + stage attention output: obuf[pix][k], pix = blk*16 + qq, pad 260
    __syncthreads();                    // all kv/pce reads done; obuf aliases pool
    float* obuf = pool;
    {
        float inv = 1.0f / l;
        ull ip = pk(inv, inv);
        float4* orow = (float4*)(obuf + (blk * 16 + qq) * 260 + h * 32);
        #pragma unroll
        for (int d4 = 0; d4 < 8; d4++) {
            float4 v;
            ull a01 = mul2(acc[d4*2+0], ip), a23 = mul2(acc[d4*2+1], ip);
            upk(a01, v.x, v.y); upk(a23, v.z, v.w);
            orow[d4] = v;
        }
    }
    __syncthreads();

    // Fused output projection: out32x128 = obuf(32x256) @ w_out.T + b_out
    // thread = (cg 32, pg 8): pg = (eb, ej); 4 channels x 4 i-positions each.
    const int cg = tid >> 3;            // 0..31 -> channels cg*4..cg*4+3
    const int pg = tid & 7;
    const int eb = pg >> 2, ej = pg & 3;
    ull accO[4][4];
    #pragma unroll
    for (int ci = 0; ci < 4; ci++)
        #pragma unroll
        for (int i = 0; i < 4; i++) accO[ci][i] = 0ULL;

    #pragma unroll 4
    for (int k4 = 0; k4 < 64; k4++) {
        ull o01[4], o23[4];
        #pragma unroll
        for (int i = 0; i < 4; i++) {
            float4 o = *(const float4*)(obuf + (eb * 16 + i * 4 + ej) * 260 + k4 * 4);
            o01[i] = pk(o.x, o.y); o23[i] = pk(o.z, o.w);
        }
        #pragma unroll
        for (int ci = 0; ci < 4; ci++) {
            float4 w4 = __ldg((const float4*)(w_out + (cg * 4 + ci) * 256 + k4 * 4));
            ull w01 = pk(w4.x, w4.y), w23 = pk(w4.z, w4.w);
            #pragma unroll
            for (int i = 0; i < 4; i++) {
                accO[ci][i] = fma2(w01, o01[i], accO[ci][i]);
                accO[ci][i] = fma2(w23, o23[i], accO[ci][i]);
            }
        }
    }

    const int hh = (R0 + eb) * 4 + ej;
    #pragma unroll
    for (int ci = 0; ci < 4; ci++) {
        int c = cg * 4 + ci;
        float bo = __ldg(b_out + c);
        float4 r;
        r.x = hsum2(accO[ci][0]) + bo; r.y = hsum2(accO[ci][1]) + bo;
        r.z = hsum2(accO[ci][2]) + bo; r.w = hsum2(accO[ci][3]) + bo;
        *(float4*)(out + ((size_t)(b * 128 + c) * 256 + hh) * 256 + P * 4) = r;
    }
}

// ---------------------------------------------------------------------------
extern "C" void kernel_launch(void* const* d_in, const int* in_sizes, int n_in,
                              void* d_out, int out_size)
{
    const float* x     = (const float*)d_in[0];
    const float* w_in  = (const float*)d_in[1];
    const float* b_in  = (const float*)d_in[2];
    const float* w_out = (const float*)d_in[3];
    const float* b_out = (const float*)d_in[4];
    const float* pce   = (const float*)d_in[5];
    float* out = (float*)d_out;

    proj_kernel<<<2048, 256>>>(x, w_in, b_in);
    attn_kernel<<<4096, 256>>>(w_out, b_out, pce, out);
}